// round 1
// baseline (speedup 1.0000x reference)
#include <cuda_runtime.h>
#include <math.h>

#define NPTS   65536
#define HNB    32
#define CIN    256
#define CMID   64
#define COUT   256
#define KPTS   15
#define KC     (KPTS*CMID)   /* 960 */
#define SLOPE  0.1f
#define EPSGN  1e-5f

// ---------------- scratch (static device globals: allocation-free) ----------------
__device__ float g_x1[(size_t)NPTS * CMID];     // 16.7 MB
__device__ float g_x2[(size_t)NPTS * CMID];     // 16.7 MB
__device__ float g_x3[(size_t)NPTS * COUT];     // 67 MB
__device__ float g_w [(size_t)NPTS * KC];       // 251 MB (weighted)
__device__ float g_stats[192];                  // 3 stages x (32 sums, 32 sumsq)

// ---------------- zero the stats accumulators ----------------
__global__ void zero_stats_kernel() {
    if (threadIdx.x < 192) g_stats[threadIdx.x] = 0.f;
}

// ---------------- generic tiled FP32 GEMM: C = scale * (A @ B) + bias ----------------
// A: M x K row-major (lda), B: K x Ncols row-major (ldb), C: M x Ncols (ldc)
// grid: (M/128, Ncols/64), block: 256 threads, 8x4 micro-tile per thread.
__global__ __launch_bounds__(256) void gemm_kernel(
    const float* __restrict__ A, int lda,
    const float* __restrict__ B, int ldb,
    const float* __restrict__ bias,
    float* __restrict__ C, int ldc,
    int K, float scale)
{
    __shared__ __align__(16) float As[32][129];   // As[k][row], conflict-free
    __shared__ __align__(16) float Bs[32][68];    // Bs[k][col], float4-aligned rows

    const int tid   = threadIdx.x;
    const int tx    = tid & 15;        // 16 col-groups
    const int ty    = tid >> 4;        // 16 row-groups
    const int rbase = blockIdx.x * 128;
    const int cbase = blockIdx.y * 64;
    const int r0    = ty * 8;
    const int c0    = tx * 4;

    float acc[8][4];
#pragma unroll
    for (int i = 0; i < 8; i++)
#pragma unroll
        for (int j = 0; j < 4; j++) acc[i][j] = 0.f;

    for (int kk = 0; kk < K; kk += 32) {
        // load A tile (128 rows x 32 k), transposed into As[k][row]
#pragma unroll
        for (int i = tid; i < 128 * 32; i += 256) {
            int r = i >> 5, k = i & 31;
            As[k][r] = A[(size_t)(rbase + r) * lda + (kk + k)];
        }
        // load B tile (32 k x 64 cols)
#pragma unroll
        for (int i = tid; i < 32 * 64; i += 256) {
            int k = i >> 6, c = i & 63;
            Bs[k][c] = B[(size_t)(kk + k) * ldb + (cbase + c)];
        }
        __syncthreads();

#pragma unroll
        for (int k = 0; k < 32; k++) {
            float a[8];
#pragma unroll
            for (int i = 0; i < 8; i++) a[i] = As[k][r0 + i];
            float4 b = *(const float4*)&Bs[k][c0];
#pragma unroll
            for (int i = 0; i < 8; i++) {
                acc[i][0] = fmaf(a[i], b.x, acc[i][0]);
                acc[i][1] = fmaf(a[i], b.y, acc[i][1]);
                acc[i][2] = fmaf(a[i], b.z, acc[i][2]);
                acc[i][3] = fmaf(a[i], b.w, acc[i][3]);
            }
        }
        __syncthreads();
    }

    float4 bv = *(const float4*)&bias[cbase + c0];
#pragma unroll
    for (int i = 0; i < 8; i++) {
        float4 v;
        v.x = fmaf(acc[i][0], scale, bv.x);
        v.y = fmaf(acc[i][1], scale, bv.y);
        v.z = fmaf(acc[i][2], scale, bv.z);
        v.w = fmaf(acc[i][3], scale, bv.w);
        *(float4*)&C[(size_t)(rbase + r0 + i) * ldc + cbase + c0] = v;
    }
}

// ---------------- group-norm stats: per-group sum & sumsq over all N points ----------------
// x: N x C, group = channel >> gshift, out[0..31]=sum, out[32..63]=sumsq
__global__ __launch_bounds__(256) void stats_kernel(
    const float* __restrict__ x, int C, int gshift, float* __restrict__ out)
{
    __shared__ float s_sum[32], s_sq[32];
    if (threadIdx.x < 32) { s_sum[threadIdx.x] = 0.f; s_sq[threadIdx.x] = 0.f; }
    __syncthreads();

    const int rpb  = 256 / C;                // rows per block step (4 or 1)
    const int ch   = threadIdx.x & (C - 1);
    const int rsub = threadIdx.x / C;

    float s = 0.f, ss = 0.f;
    for (int r = blockIdx.x * rpb + rsub; r < NPTS; r += gridDim.x * rpb) {
        float v = x[(size_t)r * C + ch];
        s += v;
        ss = fmaf(v, v, ss);
    }
    int g = ch >> gshift;
    atomicAdd(&s_sum[g], s);
    atomicAdd(&s_sq[g], ss);
    __syncthreads();
    if (threadIdx.x < 32) {
        atomicAdd(&out[threadIdx.x],      s_sum[threadIdx.x]);
        atomicAdd(&out[32 + threadIdx.x], s_sq[threadIdx.x]);
    }
}

// ---------------- apply group-norm + leaky relu in place ----------------
__global__ __launch_bounds__(256) void gn_apply_kernel(
    float* __restrict__ x, const float* __restrict__ stats,
    const float* __restrict__ gamma, const float* __restrict__ beta,
    int C, int gshift, float inv_count)
{
    __shared__ float s_mean[32], s_rstd[32];
    if (threadIdx.x < 32) {
        float m = stats[threadIdx.x] * inv_count;
        float v = stats[32 + threadIdx.x] * inv_count - m * m;
        s_mean[threadIdx.x] = m;
        s_rstd[threadIdx.x] = rsqrtf(v + EPSGN);
    }
    __syncthreads();

    size_t total = (size_t)NPTS * C;
    for (size_t i = (size_t)blockIdx.x * blockDim.x + threadIdx.x;
         i < total; i += (size_t)gridDim.x * blockDim.x) {
        int ch = (int)(i & (size_t)(C - 1));
        int g  = ch >> gshift;
        float y = (x[i] - s_mean[g]) * s_rstd[g] * gamma[ch] + beta[ch];
        x[i] = (y >= 0.f) ? y : SLOPE * y;
    }
}

// ---------------- KPConv stage A: weighted[n][k][c] = sum_h w[n][h][k] * x1n[idx][c] ----------------
// 4 points per 256-thread block; 64 channel-threads per point.
__global__ __launch_bounds__(256) void kp_weighted_kernel(
    const float* __restrict__ q_points,
    const float* __restrict__ s_points,
    const int*   __restrict__ nbr,
    const float* __restrict__ kernel_points)
{
    __shared__ int   idx_s[4][32];
    __shared__ __align__(16) float w_s[4][32][16];   // k padded 15 -> 16
    __shared__ float kp_s[48];

    const int tid  = threadIdx.x;
    if (tid < 45) kp_s[tid] = kernel_points[tid];
    const int pt   = tid >> 6;
    const int lane = tid & 63;
    const int n    = blockIdx.x * 4 + pt;
    __syncthreads();

    // phase A: geometry -> influence weights (32 threads per point)
    if (lane < 32) {
        int idx = nbr[n * HNB + lane];
        idx_s[pt][lane] = idx;
        float qx = q_points[n * 3 + 0];
        float qy = q_points[n * 3 + 1];
        float qz = q_points[n * 3 + 2];
        float dx = s_points[(size_t)idx * 3 + 0] - qx;
        float dy = s_points[(size_t)idx * 3 + 1] - qy;
        float dz = s_points[(size_t)idx * 3 + 2] - qz;
#pragma unroll
        for (int k = 0; k < KPTS; k++) {
            float ex = dx - kp_s[3 * k + 0];
            float ey = dy - kp_s[3 * k + 1];
            float ez = dz - kp_s[3 * k + 2];
            float dist = sqrtf(fmaf(ex, ex, fmaf(ey, ey, ez * ez)));
            w_s[pt][lane][k] = fmaxf(1.0f - dist, 0.0f);   // sigma = 1
        }
    }
    __syncthreads();

    // phase B: gather features and accumulate weighted (64 threads = channels)
    const int c = lane;
    float acc[KPTS];
#pragma unroll
    for (int k = 0; k < KPTS; k++) acc[k] = 0.f;

#pragma unroll 2
    for (int h0 = 0; h0 < HNB; h0 += 4) {
        float f[4];
#pragma unroll
        for (int j = 0; j < 4; j++) {
            int idx = idx_s[pt][h0 + j];
            f[j] = __ldg(&g_x1[(size_t)idx * CMID + c]);
        }
#pragma unroll
        for (int j = 0; j < 4; j++) {
            const float4* wv = (const float4*)w_s[pt][h0 + j];
            float4 wa = wv[0], wb = wv[1], wc = wv[2], wd = wv[3];
            acc[0]  = fmaf(wa.x, f[j], acc[0]);
            acc[1]  = fmaf(wa.y, f[j], acc[1]);
            acc[2]  = fmaf(wa.z, f[j], acc[2]);
            acc[3]  = fmaf(wa.w, f[j], acc[3]);
            acc[4]  = fmaf(wb.x, f[j], acc[4]);
            acc[5]  = fmaf(wb.y, f[j], acc[5]);
            acc[6]  = fmaf(wb.z, f[j], acc[6]);
            acc[7]  = fmaf(wb.w, f[j], acc[7]);
            acc[8]  = fmaf(wc.x, f[j], acc[8]);
            acc[9]  = fmaf(wc.y, f[j], acc[9]);
            acc[10] = fmaf(wc.z, f[j], acc[10]);
            acc[11] = fmaf(wc.w, f[j], acc[11]);
            acc[12] = fmaf(wd.x, f[j], acc[12]);
            acc[13] = fmaf(wd.y, f[j], acc[13]);
            acc[14] = fmaf(wd.z, f[j], acc[14]);
        }
    }

    float* wout = g_w + (size_t)n * KC + c;
#pragma unroll
    for (int k = 0; k < KPTS; k++) wout[(size_t)k * CMID] = acc[k];
}

// ---------------- final: out = leaky( GN3(x3) + s_feats ) ----------------
__global__ __launch_bounds__(256) void final_kernel(
    const float* __restrict__ x3, const float* __restrict__ stats,
    const float* __restrict__ gamma, const float* __restrict__ beta,
    const float* __restrict__ sfeats, float* __restrict__ out)
{
    __shared__ float s_mean[32], s_rstd[32];
    if (threadIdx.x < 32) {
        const float inv = 1.f / (8.f * (float)NPTS);
        float m = stats[threadIdx.x] * inv;
        float v = stats[32 + threadIdx.x] * inv - m * m;
        s_mean[threadIdx.x] = m;
        s_rstd[threadIdx.x] = rsqrtf(v + EPSGN);
    }
    __syncthreads();

    size_t total = (size_t)NPTS * COUT;
    for (size_t i = (size_t)blockIdx.x * blockDim.x + threadIdx.x;
         i < total; i += (size_t)gridDim.x * blockDim.x) {
        int ch = (int)(i & 255);
        int g  = ch >> 3;
        float y = (x3[i] - s_mean[g]) * s_rstd[g] * gamma[ch] + beta[ch] + sfeats[i];
        out[i] = (y >= 0.f) ? y : SLOPE * y;
    }
}

// ---------------- launcher ----------------
extern "C" void kernel_launch(void* const* d_in, const int* in_sizes, int n_in,
                              void* d_out, int out_size)
{
    (void)in_sizes; (void)n_in; (void)out_size;
    const float* s_feats  = (const float*)d_in[0];
    const float* q_points = (const float*)d_in[1];
    const float* s_points = (const float*)d_in[2];
    const int*   nbr      = (const int*)  d_in[3];
    const float* W1       = (const float*)d_in[4];
    const float* b1       = (const float*)d_in[5];
    const float* g1       = (const float*)d_in[6];
    const float* beta1    = (const float*)d_in[7];
    const float* kpw      = (const float*)d_in[8];
    const float* kpb      = (const float*)d_in[9];
    const float* kp       = (const float*)d_in[10];
    const float* gcg      = (const float*)d_in[11];
    const float* gcb      = (const float*)d_in[12];
    const float* W2       = (const float*)d_in[13];
    const float* b2       = (const float*)d_in[14];
    const float* g2       = (const float*)d_in[15];
    const float* beta2    = (const float*)d_in[16];
    float* out = (float*)d_out;

    float *x1, *x2, *x3, *wbuf, *stats;
    cudaGetSymbolAddress((void**)&x1,    g_x1);
    cudaGetSymbolAddress((void**)&x2,    g_x2);
    cudaGetSymbolAddress((void**)&x3,    g_x3);
    cudaGetSymbolAddress((void**)&wbuf,  g_w);
    cudaGetSymbolAddress((void**)&stats, g_stats);

    const float invN2 = 1.f / (2.f * (float)NPTS);   // GN1/GN2: 2 channels/group

    zero_stats_kernel<<<1, 256>>>();

    // unary1: x1 = s_feats @ W1 + b1
    gemm_kernel<<<dim3(NPTS / 128, 1), 256>>>(s_feats, CIN, W1, CMID, b1, x1, CMID, CIN, 1.f);
    stats_kernel<<<1024, 256>>>(x1, CMID, 1, stats + 0);
    gn_apply_kernel<<<2048, 256>>>(x1, stats + 0, g1, beta1, CMID, 1, invN2);

    // KPConv stage A: weighted
    kp_weighted_kernel<<<NPTS / 4, 256>>>(q_points, s_points, nbr, kp);

    // KPConv stage B: x2 = weighted(N x 960) @ kpw(960 x 64) / 32 + kpb
    gemm_kernel<<<dim3(NPTS / 128, 1), 256>>>(wbuf, KC, kpw, CMID, kpb, x2, CMID, KC, 1.f / 32.f);
    stats_kernel<<<1024, 256>>>(x2, CMID, 1, stats + 64);
    gn_apply_kernel<<<2048, 256>>>(x2, stats + 64, gcg, gcb, CMID, 1, invN2);

    // unary2: x3 = x2 @ W2 + b2
    gemm_kernel<<<dim3(NPTS / 128, COUT / 64), 256>>>(x2, CMID, W2, COUT, b2, x3, COUT, CMID, 1.f);
    stats_kernel<<<1024, 256>>>(x3, COUT, 3, stats + 128);

    // GN3 + residual + leaky
    final_kernel<<<2048, 256>>>(x3, stats + 128, g2, beta2, s_feats, out);
}